// round 1
// baseline (speedup 1.0000x reference)
#include <cuda_runtime.h>
#include <cuda_bf16.h>
#include <math.h>

// Problem constants
#define BB 16
#define CC 256
#define HW 1024
#define NH 8
#define HD 32
#define GN_G 8
#define GN_EPS 1e-5f

// Scratch (allocation-free: __device__ globals)
__device__ float g_qkv[BB * 3 * CC * HW];   // [b][o(768)][s]
__device__ float g_attn[BB * CC * HW];      // [b][c][s]
__device__ float g_proj[BB * CC * HW];      // [b][c][s]

// ---------------------------------------------------------------------------
// Batched GEMM: C[b] = A (shared MxK) * B[b] (KxN), all row-major, fp32.
// BM=BN=64, BK=16, 256 threads, 4x4 per thread.
// ---------------------------------------------------------------------------
#define Bb 64
#define BNt 64
#define BKt 16

__global__ void gemm_kernel(const float* __restrict__ A,
                            const float* __restrict__ Bmat,
                            float* __restrict__ Cmat,
                            int M, int N, int K,
                            long strideB, long strideC) {
    const int bz = blockIdx.z;
    const float* Bp = Bmat + (long)bz * strideB;
    float* Cp = Cmat + (long)bz * strideC;

    __shared__ float As[BKt][Bb];
    __shared__ float Bs[BKt][BNt];

    const int tid = threadIdx.x;
    const int m0 = blockIdx.y * Bb;
    const int n0 = blockIdx.x * BNt;
    const int tm = (tid >> 4) << 2;   // 0..60
    const int tn = (tid & 15) << 2;   // 0..60

    float acc[4][4];
#pragma unroll
    for (int i = 0; i < 4; i++)
#pragma unroll
        for (int j = 0; j < 4; j++) acc[i][j] = 0.f;

    const int ar = tid >> 2;            // 0..63
    const int ac = (tid & 3) << 2;      // 0,4,8,12
    const int br = tid >> 4;            // 0..15
    const int bc = (tid & 15) << 2;     // 0..60

    for (int k0 = 0; k0 < K; k0 += BKt) {
        float4 a = *reinterpret_cast<const float4*>(&A[(m0 + ar) * K + k0 + ac]);
        As[ac + 0][ar] = a.x;
        As[ac + 1][ar] = a.y;
        As[ac + 2][ar] = a.z;
        As[ac + 3][ar] = a.w;
        float4 bv = *reinterpret_cast<const float4*>(&Bp[(long)(k0 + br) * N + n0 + bc]);
        *reinterpret_cast<float4*>(&Bs[br][bc]) = bv;
        __syncthreads();

#pragma unroll
        for (int k = 0; k < BKt; k++) {
            float ra[4], rb[4];
            *reinterpret_cast<float4*>(ra) = *reinterpret_cast<const float4*>(&As[k][tm]);
            *reinterpret_cast<float4*>(rb) = *reinterpret_cast<const float4*>(&Bs[k][tn]);
#pragma unroll
            for (int i = 0; i < 4; i++)
#pragma unroll
                for (int j = 0; j < 4; j++)
                    acc[i][j] = fmaf(ra[i], rb[j], acc[i][j]);
        }
        __syncthreads();
    }

#pragma unroll
    for (int i = 0; i < 4; i++) {
        float4 v = make_float4(acc[i][0], acc[i][1], acc[i][2], acc[i][3]);
        *reinterpret_cast<float4*>(&Cp[(long)(m0 + tm + i) * N + n0 + tn]) = v;
    }
}

// ---------------------------------------------------------------------------
// Flash attention, fp32. One thread = one query row. 128 threads/block,
// 32-key chunks of K and V staged in shared (layout [d][s] in gmem).
// grid: (B*NH, HW/128)
// ---------------------------------------------------------------------------
__global__ void attn_kernel(const float* __restrict__ qkv, float* __restrict__ out) {
    const int bn = blockIdx.x;
    const int b = bn >> 3;
    const int n = bn & 7;
    const float* qg = qkv + ((long)b * (3 * CC) + n * HD) * HW;
    const float* kg = qg + (long)CC * HW;
    const float* vg = qg + (long)(2 * CC) * HW;
    const int qrow = blockIdx.y * 128 + threadIdx.x;

    float q[HD];
#pragma unroll
    for (int d = 0; d < HD; d++) q[d] = qg[d * HW + qrow];

    __shared__ float Ks[32][HD + 1];
    __shared__ float Vs[32][HD + 1];

    float m = -1e30f, l = 0.f;
    float acc[HD];
#pragma unroll
    for (int d = 0; d < HD; d++) acc[d] = 0.f;

    const float scale = 0.17677669529663687f;   // 1/sqrt(32)

    for (int j0 = 0; j0 < HW; j0 += 32) {
        for (int idx = threadIdx.x; idx < 32 * HD; idx += 128) {
            int d = idx >> 5, j = idx & 31;
            Ks[j][d] = kg[d * HW + j0 + j];
            Vs[j][d] = vg[d * HW + j0 + j];
        }
        __syncthreads();

        float s[32];
        float cmax = -1e30f;
#pragma unroll
        for (int j = 0; j < 32; j++) {
            float t = 0.f;
#pragma unroll
            for (int d = 0; d < HD; d++) t = fmaf(q[d], Ks[j][d], t);
            t *= scale;
            s[j] = t;
            cmax = fmaxf(cmax, t);
        }
        float mnew = fmaxf(m, cmax);
        float sf = __expf(m - mnew);
        l *= sf;
#pragma unroll
        for (int d = 0; d < HD; d++) acc[d] *= sf;
#pragma unroll
        for (int j = 0; j < 32; j++) {
            float p = __expf(s[j] - mnew);
            l += p;
#pragma unroll
            for (int d = 0; d < HD; d++) acc[d] = fmaf(p, Vs[j][d], acc[d]);
        }
        m = mnew;
        __syncthreads();
    }

    const float inv = 1.f / l;
    float* og = out + ((long)b * CC + n * HD) * HW + qrow;
#pragma unroll
    for (int d = 0; d < HD; d++) og[(long)d * HW] = acc[d] * inv;
}

// ---------------------------------------------------------------------------
// GroupNorm(8) + affine + residual. One block per (b, group), 256 threads.
// ---------------------------------------------------------------------------
__global__ void gn_kernel(const float* __restrict__ proj,
                          const float* __restrict__ x,
                          const float* __restrict__ gamma,
                          const float* __restrict__ beta,
                          float* __restrict__ out) {
    const int b = blockIdx.x >> 3;
    const int g = blockIdx.x & 7;
    const long base = ((long)b * CC + g * (CC / GN_G)) * HW;
    const int NEL = (CC / GN_G) * HW;   // 32768

    float sum = 0.f, sumsq = 0.f;
    for (int i = threadIdx.x; i < NEL; i += 256) {
        float v = proj[base + i];
        sum += v;
        sumsq = fmaf(v, v, sumsq);
    }
    // block reduction
    __shared__ float ssum[8], ssq[8];
    const int lane = threadIdx.x & 31, wid = threadIdx.x >> 5;
#pragma unroll
    for (int o = 16; o > 0; o >>= 1) {
        sum += __shfl_xor_sync(0xffffffffu, sum, o);
        sumsq += __shfl_xor_sync(0xffffffffu, sumsq, o);
    }
    if (lane == 0) { ssum[wid] = sum; ssq[wid] = sumsq; }
    __syncthreads();
    __shared__ float s_mean, s_inv;
    if (threadIdx.x == 0) {
        float ts = 0.f, tq = 0.f;
#pragma unroll
        for (int i = 0; i < 8; i++) { ts += ssum[i]; tq += ssq[i]; }
        float mean = ts / (float)NEL;
        float var = tq / (float)NEL - mean * mean;
        s_mean = mean;
        s_inv = rsqrtf(var + GN_EPS);
    }
    __syncthreads();
    const float mean = s_mean, inv = s_inv;

    for (int i = threadIdx.x; i < NEL; i += 256) {
        int c = g * (CC / GN_G) + (i >> 10);
        float v = (proj[base + i] - mean) * inv * gamma[c] + beta[c] + x[base + i];
        out[base + i] = v;
    }
}

// ---------------------------------------------------------------------------
extern "C" void kernel_launch(void* const* d_in, const int* in_sizes, int n_in,
                              void* d_out, int out_size) {
    const float* x      = (const float*)d_in[0];
    const float* w_qkv  = (const float*)d_in[1];
    const float* w_proj = (const float*)d_in[2];
    const float* gamma  = (const float*)d_in[3];
    const float* beta   = (const float*)d_in[4];
    float* out = (float*)d_out;

    float *qkv_p, *attn_p, *proj_p;
    cudaGetSymbolAddress((void**)&qkv_p, g_qkv);
    cudaGetSymbolAddress((void**)&attn_p, g_attn);
    cudaGetSymbolAddress((void**)&proj_p, g_proj);

    // 1) qkv GEMM: per batch, W[768,256] * X_b[256,1024]
    {
        dim3 grid(HW / BNt, (3 * CC) / Bb, BB);
        gemm_kernel<<<grid, 256>>>(w_qkv, x, qkv_p,
                                   3 * CC, HW, CC,
                                   (long)CC * HW, (long)3 * CC * HW);
    }
    // 2) attention
    {
        dim3 grid(BB * NH, HW / 128);
        attn_kernel<<<grid, 128>>>(qkv_p, attn_p);
    }
    // 3) proj GEMM: per batch, Wp[256,256] * attn_b[256,1024]
    {
        dim3 grid(HW / BNt, CC / Bb, BB);
        gemm_kernel<<<grid, 256>>>(w_proj, attn_p, proj_p,
                                   CC, HW, CC,
                                   (long)CC * HW, (long)CC * HW);
    }
    // 4) GroupNorm + residual
    {
        gn_kernel<<<BB * GN_G, 256>>>(proj_p, x, gamma, beta, out);
    }
}

// round 4
// speedup vs baseline: 2.1567x; 2.1567x over previous
#include <cuda_runtime.h>
#include <cuda_bf16.h>
#include <math.h>
#include <stdint.h>

#define BB 16
#define CC 256
#define HW 1024
#define NH 8
#define HD 32
#define GN_G 8
#define GN_EPS 1e-5f

// Scratch
__device__ float g_qkv[BB * 3 * CC * HW];   // [b][o(768)][s]
__device__ float g_attn[BB * CC * HW];      // [b][c][s]
__device__ float g_proj[BB * CC * HW];      // [b][c][s]

// ---------------------------------------------------------------------------
// helpers
// ---------------------------------------------------------------------------
__device__ __forceinline__ uint32_t pk(unsigned short lo, unsigned short hi) {
    return (uint32_t)lo | ((uint32_t)hi << 16);
}
__device__ __forceinline__ void split2(float v, unsigned short& h, unsigned short& l) {
    __nv_bfloat16 bh = __float2bfloat16(v);
    float r = v - __bfloat162float(bh);
    __nv_bfloat16 bl = __float2bfloat16(r);
    h = *(unsigned short*)&bh;
    l = *(unsigned short*)&bl;
}
__device__ __forceinline__ void mma16816(float* c, const uint32_t* a, const uint32_t* b) {
    asm volatile(
        "mma.sync.aligned.m16n8k16.row.col.f32.bf16.bf16.f32 "
        "{%0,%1,%2,%3}, {%4,%5,%6,%7}, {%8,%9}, {%0,%1,%2,%3};"
        : "+f"(c[0]), "+f"(c[1]), "+f"(c[2]), "+f"(c[3])
        : "r"(a[0]), "r"(a[1]), "r"(a[2]), "r"(a[3]), "r"(b[0]), "r"(b[1]));
}

// ---------------------------------------------------------------------------
// Batched GEMM via mma.sync, bf16 3-term split, fp32 in/out.
// C[b] = W[M,256] * X[b][256,1024].  BM=64, BN=128, BK=32, 256 threads.
// ---------------------------------------------------------------------------
#define GLDA 40
#define GLDB 136

__global__ void __launch_bounds__(256) mma_gemm(const float* __restrict__ A,
                                                const float* __restrict__ B,
                                                float* __restrict__ C,
                                                long sB, long sC) {
    const int bz = blockIdx.z;
    const float* Bp = B + (long)bz * sB;
    float* Cp = C + (long)bz * sC;
    const int m0 = blockIdx.y * 64, n0 = blockIdx.x * 128;
    const int tid = threadIdx.x, w = tid >> 5, lane = tid & 31;
    const int g = lane >> 2, tg = lane & 3;
    const int wm = w >> 2, wn = w & 3;

    __shared__ __nv_bfloat16 Wh[64 * GLDA], Wl[64 * GLDA];
    __shared__ __nv_bfloat16 Xh[32 * GLDB], Xl[32 * GLDB];

    float acc[2][4][4];
#pragma unroll
    for (int mt = 0; mt < 2; mt++)
#pragma unroll
        for (int nt = 0; nt < 4; nt++)
#pragma unroll
            for (int i = 0; i < 4; i++) acc[mt][nt][i] = 0.f;

    for (int k0 = 0; k0 < 256; k0 += 32) {
        float wv[8], xv[16];
#pragma unroll
        for (int p = 0; p < 8; p++) {
            int idx = p * 256 + tid;
            wv[p] = A[(m0 + (idx >> 5)) * 256 + k0 + (idx & 31)];
        }
#pragma unroll
        for (int p = 0; p < 16; p++) {
            int idx = p * 256 + tid;
            xv[p] = Bp[(long)(k0 + (idx >> 7)) * 1024 + n0 + (idx & 127)];
        }
        __syncthreads();
#pragma unroll
        for (int p = 0; p < 8; p++) {
            int idx = p * 256 + tid;
            int r = idx >> 5, c = idx & 31;
            unsigned short h, l;
            split2(wv[p], h, l);
            ((unsigned short*)Wh)[r * GLDA + c] = h;
            ((unsigned short*)Wl)[r * GLDA + c] = l;
        }
#pragma unroll
        for (int p = 0; p < 16; p++) {
            int idx = p * 256 + tid;
            int r = idx >> 7, c = idx & 127;
            unsigned short h, l;
            split2(xv[p], h, l);
            ((unsigned short*)Xh)[r * GLDB + c] = h;
            ((unsigned short*)Xl)[r * GLDB + c] = l;
        }
        __syncthreads();

        const unsigned short* XH = (const unsigned short*)Xh;
        const unsigned short* XL = (const unsigned short*)Xl;
#pragma unroll
        for (int kc = 0; kc < 2; kc++) {
            uint32_t ah[2][4], al[2][4];
#pragma unroll
            for (int mt = 0; mt < 2; mt++) {
                int rb = wm * 32 + mt * 16 + g;
                int cb = kc * 16 + tg * 2;
                ah[mt][0] = *(const uint32_t*)&Wh[rb * GLDA + cb];
                ah[mt][1] = *(const uint32_t*)&Wh[(rb + 8) * GLDA + cb];
                ah[mt][2] = *(const uint32_t*)&Wh[rb * GLDA + cb + 8];
                ah[mt][3] = *(const uint32_t*)&Wh[(rb + 8) * GLDA + cb + 8];
                al[mt][0] = *(const uint32_t*)&Wl[rb * GLDA + cb];
                al[mt][1] = *(const uint32_t*)&Wl[(rb + 8) * GLDA + cb];
                al[mt][2] = *(const uint32_t*)&Wl[rb * GLDA + cb + 8];
                al[mt][3] = *(const uint32_t*)&Wl[(rb + 8) * GLDA + cb + 8];
            }
            uint32_t bh[4][2], bl[4][2];
#pragma unroll
            for (int nt = 0; nt < 4; nt++) {
                int cn = wn * 32 + nt * 8 + g;
                int kb = kc * 16 + tg * 2;
                bh[nt][0] = pk(XH[kb * GLDB + cn], XH[(kb + 1) * GLDB + cn]);
                bh[nt][1] = pk(XH[(kb + 8) * GLDB + cn], XH[(kb + 9) * GLDB + cn]);
                bl[nt][0] = pk(XL[kb * GLDB + cn], XL[(kb + 1) * GLDB + cn]);
                bl[nt][1] = pk(XL[(kb + 8) * GLDB + cn], XL[(kb + 9) * GLDB + cn]);
            }
#pragma unroll
            for (int mt = 0; mt < 2; mt++)
#pragma unroll
                for (int nt = 0; nt < 4; nt++) {
                    mma16816(acc[mt][nt], ah[mt], bh[nt]);
                    mma16816(acc[mt][nt], ah[mt], bl[nt]);
                    mma16816(acc[mt][nt], al[mt], bh[nt]);
                }
        }
        __syncthreads();
    }

#pragma unroll
    for (int mt = 0; mt < 2; mt++)
#pragma unroll
        for (int nt = 0; nt < 4; nt++) {
            int row = m0 + wm * 32 + mt * 16 + g;
            int col = n0 + wn * 32 + nt * 8 + tg * 2;
            *(float2*)&Cp[(long)row * 1024 + col] =
                make_float2(acc[mt][nt][0], acc[mt][nt][1]);
            *(float2*)&Cp[(long)(row + 8) * 1024 + col] =
                make_float2(acc[mt][nt][2], acc[mt][nt][3]);
        }
}

// ---------------------------------------------------------------------------
// Flash attention via mma.sync, bf16 3-term split, fp32 softmax.
// Block: 256 threads (8 warps), 128 queries, one (b,h). Key chunks of 64.
// grid: (128 bh, 8 qtiles)
// ---------------------------------------------------------------------------
#define ALQ 40
#define ALK 72
#define ALV 34
#define OSL 132

__global__ void __launch_bounds__(256) attn_mma(const float* __restrict__ qkv,
                                                float* __restrict__ out) {
    __shared__ __align__(16) char smembuf[38400];
    __nv_bfloat16* Qh = (__nv_bfloat16*)smembuf;                    // 10240 B
    __nv_bfloat16* Ql = (__nv_bfloat16*)(smembuf + 10240);          // 10240 B
    __nv_bfloat16* Kh = (__nv_bfloat16*)(smembuf + 20480);          // 4608 B
    __nv_bfloat16* Kl = (__nv_bfloat16*)(smembuf + 25088);          // 4608 B
    __nv_bfloat16* Vh = (__nv_bfloat16*)(smembuf + 29696);          // 4352 B
    __nv_bfloat16* Vl = (__nv_bfloat16*)(smembuf + 34048);          // 4352 B
    float* Os = (float*)smembuf;  // aliases Q region after mainloop (16896 B)

    const int bh = blockIdx.x;
    const int b = bh >> 3, h = bh & 7;
    const int i0 = blockIdx.y * 128;
    const float* qg = qkv + ((long)b * 768 + h * 32) * 1024;
    const float* kg = qg + 256 * 1024;
    const float* vg = qg + 512 * 1024;

    const int tid = threadIdx.x, w = tid >> 5, lane = tid & 31;
    const int g = lane >> 2, tg = lane & 3;
    const float scale = 0.17677669529663687f;  // 1/sqrt(32)

    // Load Q tile (128 x 32), pre-scaled, split hi/lo
#pragma unroll
    for (int p = 0; p < 16; p++) {
        int idx = p * 256 + tid;
        int i = idx & 127, d = idx >> 7;
        float v = qg[(long)d * 1024 + i0 + i] * scale;
        unsigned short hh, ll;
        split2(v, hh, ll);
        ((unsigned short*)Qh)[i * ALQ + d] = hh;
        ((unsigned short*)Ql)[i * ALQ + d] = ll;
    }
    __syncthreads();

    // Preload Q frags (warp w owns rows w*16 .. w*16+15)
    uint32_t qh[2][4], ql[2][4];
#pragma unroll
    for (int kc = 0; kc < 2; kc++) {
        int rb = w * 16 + g;
        int cb = kc * 16 + tg * 2;
        qh[kc][0] = *(const uint32_t*)&Qh[rb * ALQ + cb];
        qh[kc][1] = *(const uint32_t*)&Qh[(rb + 8) * ALQ + cb];
        qh[kc][2] = *(const uint32_t*)&Qh[rb * ALQ + cb + 8];
        qh[kc][3] = *(const uint32_t*)&Qh[(rb + 8) * ALQ + cb + 8];
        ql[kc][0] = *(const uint32_t*)&Ql[rb * ALQ + cb];
        ql[kc][1] = *(const uint32_t*)&Ql[(rb + 8) * ALQ + cb];
        ql[kc][2] = *(const uint32_t*)&Ql[rb * ALQ + cb + 8];
        ql[kc][3] = *(const uint32_t*)&Ql[(rb + 8) * ALQ + cb + 8];
    }

    float mrow[2] = {-1e30f, -1e30f};
    float lrow[2] = {0.f, 0.f};
    float oacc[4][4];
#pragma unroll
    for (int nt = 0; nt < 4; nt++)
#pragma unroll
        for (int i = 0; i < 4; i++) oacc[nt][i] = 0.f;

    for (int j0 = 0; j0 < HW; j0 += 64) {
        __syncthreads();
        // K chunk: [d=32][j=64] ; V chunk: [j=64][d=32]
#pragma unroll
        for (int p = 0; p < 8; p++) {
            int idx = p * 256 + tid;
            int j = idx & 63, d = idx >> 6;
            float kvv = kg[(long)d * 1024 + j0 + j];
            unsigned short hh, ll;
            split2(kvv, hh, ll);
            ((unsigned short*)Kh)[d * ALK + j] = hh;
            ((unsigned short*)Kl)[d * ALK + j] = ll;
            float vvv = vg[(long)d * 1024 + j0 + j];
            split2(vvv, hh, ll);
            ((unsigned short*)Vh)[j * ALV + d] = hh;
            ((unsigned short*)Vl)[j * ALV + d] = ll;
        }
        __syncthreads();

        // S = Q K^T  (16 x 64 per warp)
        float s[8][4];
#pragma unroll
        for (int nt = 0; nt < 8; nt++)
#pragma unroll
            for (int i = 0; i < 4; i++) s[nt][i] = 0.f;

        const unsigned short* KH = (const unsigned short*)Kh;
        const unsigned short* KL = (const unsigned short*)Kl;
#pragma unroll
        for (int kc = 0; kc < 2; kc++) {
            int kb = kc * 16 + tg * 2;
#pragma unroll
            for (int nt = 0; nt < 8; nt++) {
                int cn = nt * 8 + g;
                uint32_t bhf[2], blf[2];
                bhf[0] = pk(KH[kb * ALK + cn], KH[(kb + 1) * ALK + cn]);
                bhf[1] = pk(KH[(kb + 8) * ALK + cn], KH[(kb + 9) * ALK + cn]);
                blf[0] = pk(KL[kb * ALK + cn], KL[(kb + 1) * ALK + cn]);
                blf[1] = pk(KL[(kb + 8) * ALK + cn], KL[(kb + 9) * ALK + cn]);
                mma16816(s[nt], qh[kc], bhf);
                mma16816(s[nt], qh[kc], blf);
                mma16816(s[nt], ql[kc], bhf);
            }
        }

        // online softmax (rows g and g+8)
        float sc[2];
#pragma unroll
        for (int r = 0; r < 2; r++) {
            float mx = -1e30f;
#pragma unroll
            for (int nt = 0; nt < 8; nt++)
                mx = fmaxf(mx, fmaxf(s[nt][2 * r], s[nt][2 * r + 1]));
            mx = fmaxf(mx, __shfl_xor_sync(0xffffffffu, mx, 1));
            mx = fmaxf(mx, __shfl_xor_sync(0xffffffffu, mx, 2));
            float mn = fmaxf(mrow[r], mx);
            sc[r] = __expf(mrow[r] - mn);
            mrow[r] = mn;
            float ls = 0.f;
#pragma unroll
            for (int nt = 0; nt < 8; nt++) {
                float p0 = __expf(s[nt][2 * r] - mn);
                float p1 = __expf(s[nt][2 * r + 1] - mn);
                s[nt][2 * r] = p0;
                s[nt][2 * r + 1] = p1;
                ls += p0 + p1;
            }
            ls += __shfl_xor_sync(0xffffffffu, ls, 1);
            ls += __shfl_xor_sync(0xffffffffu, ls, 2);
            lrow[r] = lrow[r] * sc[r] + ls;
        }
#pragma unroll
        for (int nt = 0; nt < 4; nt++) {
            oacc[nt][0] *= sc[0];
            oacc[nt][1] *= sc[0];
            oacc[nt][2] *= sc[1];
            oacc[nt][3] *= sc[1];
        }

        // PV: P frags from S, B from Vs
        const unsigned short* VH = (const unsigned short*)Vh;
        const unsigned short* VL = (const unsigned short*)Vl;
#pragma unroll
        for (int kc2 = 0; kc2 < 4; kc2++) {
            uint32_t ah[4], al2[4];
            unsigned short h0, l0, h1, l1;
            split2(s[2 * kc2][0], h0, l0);
            split2(s[2 * kc2][1], h1, l1);
            ah[0] = pk(h0, h1); al2[0] = pk(l0, l1);
            split2(s[2 * kc2][2], h0, l0);
            split2(s[2 * kc2][3], h1, l1);
            ah[1] = pk(h0, h1); al2[1] = pk(l0, l1);
            split2(s[2 * kc2 + 1][0], h0, l0);
            split2(s[2 * kc2 + 1][1], h1, l1);
            ah[2] = pk(h0, h1); al2[2] = pk(l0, l1);
            split2(s[2 * kc2 + 1][2], h0, l0);
            split2(s[2 * kc2 + 1][3], h1, l1);
            ah[3] = pk(h0, h1); al2[3] = pk(l0, l1);

            int kb = kc2 * 16 + tg * 2;
#pragma unroll
            for (int nt2 = 0; nt2 < 4; nt2++) {
                int cn = nt2 * 8 + g;
                uint32_t bhf[2], blf[2];
                bhf[0] = pk(VH[kb * ALV + cn], VH[(kb + 1) * ALV + cn]);
                bhf[1] = pk(VH[(kb + 8) * ALV + cn], VH[(kb + 9) * ALV + cn]);
                blf[0] = pk(VL[kb * ALV + cn], VL[(kb + 1) * ALV + cn]);
                blf[1] = pk(VL[(kb + 8) * ALV + cn], VL[(kb + 9) * ALV + cn]);
                mma16816(oacc[nt2], ah, bhf);
                mma16816(oacc[nt2], ah, blf);
                mma16816(oacc[nt2], al2, bhf);
            }
        }
    }

    // normalize + transpose through smem (aliases Q region), coalesced store
    float inv0 = 1.f / lrow[0], inv1 = 1.f / lrow[1];
#pragma unroll
    for (int nt2 = 0; nt2 < 4; nt2++) {
        int d = nt2 * 8 + tg * 2;
        int irow = w * 16 + g;
        Os[d * OSL + irow] = oacc[nt2][0] * inv0;
        Os[(d + 1) * OSL + irow] = oacc[nt2][1] * inv0;
        Os[d * OSL + irow + 8] = oacc[nt2][2] * inv1;
        Os[(d + 1) * OSL + irow + 8] = oacc[nt2][3] * inv1;
    }
    __syncthreads();

    float* ob = out + ((long)b * 256 + h * 32) * 1024;
#pragma unroll
    for (int p = 0; p < 4; p++) {
        int idx = p * 256 + tid;
        int c = idx >> 5, i4 = idx & 31;
        float4 v = *(const float4*)&Os[c * OSL + i4 * 4];
        *(float4*)&ob[(long)c * 1024 + i0 + i4 * 4] = v;
    }
}

// ---------------------------------------------------------------------------
// GroupNorm(8) + affine + residual. One block per (b, group), 512 threads.
// ---------------------------------------------------------------------------
__global__ void __launch_bounds__(512) gn_kernel(const float* __restrict__ proj,
                                                 const float* __restrict__ x,
                                                 const float* __restrict__ gamma,
                                                 const float* __restrict__ beta,
                                                 float* __restrict__ out) {
    const int b = blockIdx.x >> 3;
    const int g = blockIdx.x & 7;
    const long base = ((long)b * CC + g * 32) * HW;
    const float4* p4 = (const float4*)(proj + base);
    const float4* x4 = (const float4*)(x + base);
    float4* o4 = (float4*)(out + base);
    const int N4 = 8192;

    float s = 0.f, q = 0.f;
#pragma unroll 4
    for (int i = threadIdx.x; i < N4; i += 512) {
        float4 v = p4[i];
        s += v.x + v.y + v.z + v.w;
        q = fmaf(v.x, v.x, q); q = fmaf(v.y, v.y, q);
        q = fmaf(v.z, v.z, q); q = fmaf(v.w, v.w, q);
    }
    __shared__ float ss[16], sq[16];
    const int lane = threadIdx.x & 31, wid = threadIdx.x >> 5;
#pragma unroll
    for (int o = 16; o > 0; o >>= 1) {
        s += __shfl_xor_sync(0xffffffffu, s, o);
        q += __shfl_xor_sync(0xffffffffu, q, o);
    }
    if (lane == 0) { ss[wid] = s; sq[wid] = q; }
    __syncthreads();
    __shared__ float s_mean, s_inv;
    if (threadIdx.x == 0) {
        float ts = 0.f, tq = 0.f;
#pragma unroll
        for (int i = 0; i < 16; i++) { ts += ss[i]; tq += sq[i]; }
        float mean = ts / 32768.f;
        float var = tq / 32768.f - mean * mean;
        s_mean = mean;
        s_inv = rsqrtf(var + GN_EPS);
    }
    __syncthreads();
    const float mean = s_mean, inv = s_inv;

#pragma unroll 4
    for (int i = threadIdx.x; i < N4; i += 512) {
        int c = g * 32 + (i >> 8);
        float ga = gamma[c] * inv, be = beta[c];
        float4 v = p4[i], xv = x4[i], o;
        o.x = (v.x - mean) * ga + be + xv.x;
        o.y = (v.y - mean) * ga + be + xv.y;
        o.z = (v.z - mean) * ga + be + xv.z;
        o.w = (v.w - mean) * ga + be + xv.w;
        o4[i] = o;
    }
}

// ---------------------------------------------------------------------------
extern "C" void kernel_launch(void* const* d_in, const int* in_sizes, int n_in,
                              void* d_out, int out_size) {
    const float* x      = (const float*)d_in[0];
    const float* w_qkv  = (const float*)d_in[1];
    const float* w_proj = (const float*)d_in[2];
    const float* gamma  = (const float*)d_in[3];
    const float* beta   = (const float*)d_in[4];
    float* out = (float*)d_out;

    float *qkv_p, *attn_p, *proj_p;
    cudaGetSymbolAddress((void**)&qkv_p, g_qkv);
    cudaGetSymbolAddress((void**)&attn_p, g_attn);
    cudaGetSymbolAddress((void**)&proj_p, g_proj);

    // 1) qkv GEMM: W[768,256] * X_b[256,1024]
    mma_gemm<<<dim3(8, 12, 16), 256>>>(w_qkv, x, qkv_p,
                                       (long)CC * HW, (long)3 * CC * HW);
    // 2) attention
    attn_mma<<<dim3(128, 8), 256>>>(qkv_p, attn_p);
    // 3) proj GEMM: Wp[256,256] * attn_b[256,1024]
    mma_gemm<<<dim3(8, 4, 16), 256>>>(w_proj, attn_p, proj_p,
                                      (long)CC * HW, (long)CC * HW);
    // 4) GroupNorm + residual
    gn_kernel<<<BB * GN_G, 512>>>(proj_p, x, gamma, beta, out);
}

// round 5
// speedup vs baseline: 2.5973x; 1.2043x over previous
#include <cuda_runtime.h>
#include <cuda_bf16.h>
#include <math.h>
#include <stdint.h>

#define BB 16
#define CC 256
#define HW 1024
#define NH 8
#define HD 32
#define GN_G 8
#define GN_EPS 1e-5f

// Scratch
__device__ float g_qkv[BB * 3 * CC * HW];   // [b][o(768)][s]
__device__ float g_attn[BB * CC * HW];      // [b][c][s]
__device__ float g_proj[BB * CC * HW];      // [b][c][s]

// ---------------------------------------------------------------------------
// helpers
// ---------------------------------------------------------------------------
__device__ __forceinline__ uint32_t pk(unsigned short lo, unsigned short hi) {
    return (uint32_t)lo | ((uint32_t)hi << 16);
}
__device__ __forceinline__ void split2(float v, unsigned short& h, unsigned short& l) {
    __nv_bfloat16 bh = __float2bfloat16(v);
    float r = v - __bfloat162float(bh);
    __nv_bfloat16 bl = __float2bfloat16(r);
    h = *(unsigned short*)&bh;
    l = *(unsigned short*)&bl;
}
__device__ __forceinline__ void mma16816(float* c, const uint32_t* a, const uint32_t* b) {
    asm volatile(
        "mma.sync.aligned.m16n8k16.row.col.f32.bf16.bf16.f32 "
        "{%0,%1,%2,%3}, {%4,%5,%6,%7}, {%8,%9}, {%0,%1,%2,%3};"
        : "+f"(c[0]), "+f"(c[1]), "+f"(c[2]), "+f"(c[3])
        : "r"(a[0]), "r"(a[1]), "r"(a[2]), "r"(a[3]), "r"(b[0]), "r"(b[1]));
}
// tf32 mma m16n8k8
__device__ __forceinline__ void mma1688(float* c, const uint32_t* a, const uint32_t* b) {
    asm volatile(
        "mma.sync.aligned.m16n8k8.row.col.f32.tf32.tf32.f32 "
        "{%0,%1,%2,%3}, {%4,%5,%6,%7}, {%8,%9}, {%0,%1,%2,%3};"
        : "+f"(c[0]), "+f"(c[1]), "+f"(c[2]), "+f"(c[3])
        : "r"(a[0]), "r"(a[1]), "r"(a[2]), "r"(a[3]), "r"(b[0]), "r"(b[1]));
}
__device__ __forceinline__ uint32_t tf32r(float v) {
    uint32_t r;
    asm("cvt.rna.tf32.f32 %0, %1;" : "=r"(r) : "f"(v));
    return r;
}

// ---------------------------------------------------------------------------
// Batched GEMM via mma.sync, bf16 3-term split, fp32 in/out. (unchanged)
// C[b] = W[M,256] * X[b][256,1024].  BM=64, BN=128, BK=32, 256 threads.
// ---------------------------------------------------------------------------
#define GLDA 40
#define GLDB 136

__global__ void __launch_bounds__(256) mma_gemm(const float* __restrict__ A,
                                                const float* __restrict__ B,
                                                float* __restrict__ C,
                                                long sB, long sC) {
    const int bz = blockIdx.z;
    const float* Bp = B + (long)bz * sB;
    float* Cp = C + (long)bz * sC;
    const int m0 = blockIdx.y * 64, n0 = blockIdx.x * 128;
    const int tid = threadIdx.x, w = tid >> 5, lane = tid & 31;
    const int g = lane >> 2, tg = lane & 3;
    const int wm = w >> 2, wn = w & 3;

    __shared__ __nv_bfloat16 Wh[64 * GLDA], Wl[64 * GLDA];
    __shared__ __nv_bfloat16 Xh[32 * GLDB], Xl[32 * GLDB];

    float acc[2][4][4];
#pragma unroll
    for (int mt = 0; mt < 2; mt++)
#pragma unroll
        for (int nt = 0; nt < 4; nt++)
#pragma unroll
            for (int i = 0; i < 4; i++) acc[mt][nt][i] = 0.f;

    for (int k0 = 0; k0 < 256; k0 += 32) {
        float wv[8], xv[16];
#pragma unroll
        for (int p = 0; p < 8; p++) {
            int idx = p * 256 + tid;
            wv[p] = A[(m0 + (idx >> 5)) * 256 + k0 + (idx & 31)];
        }
#pragma unroll
        for (int p = 0; p < 16; p++) {
            int idx = p * 256 + tid;
            xv[p] = Bp[(long)(k0 + (idx >> 7)) * 1024 + n0 + (idx & 127)];
        }
        __syncthreads();
#pragma unroll
        for (int p = 0; p < 8; p++) {
            int idx = p * 256 + tid;
            int r = idx >> 5, c = idx & 31;
            unsigned short h, l;
            split2(wv[p], h, l);
            ((unsigned short*)Wh)[r * GLDA + c] = h;
            ((unsigned short*)Wl)[r * GLDA + c] = l;
        }
#pragma unroll
        for (int p = 0; p < 16; p++) {
            int idx = p * 256 + tid;
            int r = idx >> 7, c = idx & 127;
            unsigned short h, l;
            split2(xv[p], h, l);
            ((unsigned short*)Xh)[r * GLDB + c] = h;
            ((unsigned short*)Xl)[r * GLDB + c] = l;
        }
        __syncthreads();

        const unsigned short* XH = (const unsigned short*)Xh;
        const unsigned short* XL = (const unsigned short*)Xl;
#pragma unroll
        for (int kc = 0; kc < 2; kc++) {
            uint32_t ah[2][4], al[2][4];
#pragma unroll
            for (int mt = 0; mt < 2; mt++) {
                int rb = wm * 32 + mt * 16 + g;
                int cb = kc * 16 + tg * 2;
                ah[mt][0] = *(const uint32_t*)&Wh[rb * GLDA + cb];
                ah[mt][1] = *(const uint32_t*)&Wh[(rb + 8) * GLDA + cb];
                ah[mt][2] = *(const uint32_t*)&Wh[rb * GLDA + cb + 8];
                ah[mt][3] = *(const uint32_t*)&Wh[(rb + 8) * GLDA + cb + 8];
                al[mt][0] = *(const uint32_t*)&Wl[rb * GLDA + cb];
                al[mt][1] = *(const uint32_t*)&Wl[(rb + 8) * GLDA + cb];
                al[mt][2] = *(const uint32_t*)&Wl[rb * GLDA + cb + 8];
                al[mt][3] = *(const uint32_t*)&Wl[(rb + 8) * GLDA + cb + 8];
            }
            uint32_t bh[4][2], bl[4][2];
#pragma unroll
            for (int nt = 0; nt < 4; nt++) {
                int cn = wn * 32 + nt * 8 + g;
                int kb = kc * 16 + tg * 2;
                bh[nt][0] = pk(XH[kb * GLDB + cn], XH[(kb + 1) * GLDB + cn]);
                bh[nt][1] = pk(XH[(kb + 8) * GLDB + cn], XH[(kb + 9) * GLDB + cn]);
                bl[nt][0] = pk(XL[kb * GLDB + cn], XL[(kb + 1) * GLDB + cn]);
                bl[nt][1] = pk(XL[(kb + 8) * GLDB + cn], XL[(kb + 9) * GLDB + cn]);
            }
#pragma unroll
            for (int mt = 0; mt < 2; mt++)
#pragma unroll
                for (int nt = 0; nt < 4; nt++) {
                    mma16816(acc[mt][nt], ah[mt], bh[nt]);
                    mma16816(acc[mt][nt], ah[mt], bl[nt]);
                    mma16816(acc[mt][nt], al[mt], bh[nt]);
                }
        }
        __syncthreads();
    }

#pragma unroll
    for (int mt = 0; mt < 2; mt++)
#pragma unroll
        for (int nt = 0; nt < 4; nt++) {
            int row = m0 + wm * 32 + mt * 16 + g;
            int col = n0 + wn * 32 + nt * 8 + tg * 2;
            *(float2*)&Cp[(long)row * 1024 + col] =
                make_float2(acc[mt][nt][0], acc[mt][nt][1]);
            *(float2*)&Cp[(long)(row + 8) * 1024 + col] =
                make_float2(acc[mt][nt][2], acc[mt][nt][3]);
        }
}

// ---------------------------------------------------------------------------
// Flash attention via single-pass tf32 mma (m16n8k8), fp32 softmax.
// 256 threads (8 warps), 128 queries per block, key chunks of 32.
// K, V kept in natural [d][j] layout; P staged per-warp in smem.
// grid: (128 bh, 8 qtiles)
// ---------------------------------------------------------------------------
#define PS_LD 40
#define KS_LD 40
#define VS_LD 36
#define OSL 132

__global__ void __launch_bounds__(256) attn_tf32(const float* __restrict__ qkv,
                                                 float* __restrict__ out) {
    __shared__ float Ps[8 * 16 * PS_LD];   // 20480 B (reused as Os in epilogue)
    __shared__ float Ks[32 * KS_LD];       // 5120 B
    __shared__ float Vs[32 * VS_LD];       // 4608 B

    const int bh = blockIdx.x;
    const int b = bh >> 3, h = bh & 7;
    const int i0 = blockIdx.y * 128;
    const float* qg = qkv + ((long)b * 768 + h * 32) * 1024;
    const float* kg = qg + 256 * 1024;
    const float* vg = qg + 512 * 1024;

    const int tid = threadIdx.x, w = tid >> 5, lane = tid & 31;
    const int g = lane >> 2, tg = lane & 3;
    const float scale = 0.17677669529663687f;  // 1/sqrt(32)

    // Q fragments direct from global, pre-scaled, rna-rounded to tf32.
    // A-frag (m16n8k8): a0=(g, tg), a1=(g+8, tg), a2=(g, tg+4), a3=(g+8, tg+4)
    uint32_t qf[4][4];
    {
        const int r0 = i0 + w * 16 + g;
#pragma unroll
        for (int kc = 0; kc < 4; kc++) {
            int d0 = kc * 8 + tg, d1 = d0 + 4;
            qf[kc][0] = tf32r(qg[(long)d0 * 1024 + r0] * scale);
            qf[kc][1] = tf32r(qg[(long)d0 * 1024 + r0 + 8] * scale);
            qf[kc][2] = tf32r(qg[(long)d1 * 1024 + r0] * scale);
            qf[kc][3] = tf32r(qg[(long)d1 * 1024 + r0 + 8] * scale);
        }
    }

    float mrow[2] = {-1e30f, -1e30f};
    float lrow[2] = {0.f, 0.f};
    float oacc[4][4];
#pragma unroll
    for (int nt = 0; nt < 4; nt++)
#pragma unroll
        for (int i = 0; i < 4; i++) oacc[nt][i] = 0.f;

    float* Pw = Ps + w * 16 * PS_LD;

    for (int j0 = 0; j0 < HW; j0 += 32) {
        __syncthreads();
        // Fill K,V chunk (32 d x 32 j each), natural [d][j] layout, coalesced.
#pragma unroll
        for (int p = 0; p < 4; p++) {
            int idx = p * 256 + tid;
            int j = idx & 31, d = idx >> 5;
            Ks[d * KS_LD + j] = __uint_as_float(tf32r(kg[(long)d * 1024 + j0 + j]));
            Vs[d * VS_LD + j] = __uint_as_float(tf32r(vg[(long)d * 1024 + j0 + j]));
        }
        __syncthreads();

        // S = Q K^T : 16x32 per warp, 16 mmas
        float s[4][4];
#pragma unroll
        for (int nt = 0; nt < 4; nt++)
#pragma unroll
            for (int i = 0; i < 4; i++) s[nt][i] = 0.f;
#pragma unroll
        for (int kc = 0; kc < 4; kc++) {
            int kb = kc * 8;
#pragma unroll
            for (int nt = 0; nt < 4; nt++) {
                int cn = nt * 8 + g;
                uint32_t bf[2];
                bf[0] = __float_as_uint(Ks[(kb + tg) * KS_LD + cn]);
                bf[1] = __float_as_uint(Ks[(kb + tg + 4) * KS_LD + cn]);
                mma1688(s[nt], qf[kc], bf);
            }
        }

        // online softmax (rows g and g+8); l accumulated from tf32-rounded P
        float sc[2];
#pragma unroll
        for (int r = 0; r < 2; r++) {
            float mx = -1e30f;
#pragma unroll
            for (int nt = 0; nt < 4; nt++)
                mx = fmaxf(mx, fmaxf(s[nt][2 * r], s[nt][2 * r + 1]));
            mx = fmaxf(mx, __shfl_xor_sync(0xffffffffu, mx, 1));
            mx = fmaxf(mx, __shfl_xor_sync(0xffffffffu, mx, 2));
            float mn = fmaxf(mrow[r], mx);
            sc[r] = __expf(mrow[r] - mn);
            mrow[r] = mn;
            float ls = 0.f;
#pragma unroll
            for (int nt = 0; nt < 4; nt++) {
                float p0 = __uint_as_float(tf32r(__expf(s[nt][2 * r] - mn)));
                float p1 = __uint_as_float(tf32r(__expf(s[nt][2 * r + 1] - mn)));
                s[nt][2 * r] = p0;
                s[nt][2 * r + 1] = p1;
                ls += p0 + p1;
            }
            ls += __shfl_xor_sync(0xffffffffu, ls, 1);
            ls += __shfl_xor_sync(0xffffffffu, ls, 2);
            lrow[r] = lrow[r] * sc[r] + ls;
        }
#pragma unroll
        for (int nt = 0; nt < 4; nt++) {
            oacc[nt][0] *= sc[0];
            oacc[nt][1] *= sc[0];
            oacc[nt][2] *= sc[1];
            oacc[nt][3] *= sc[1];
        }

        // Stage P to per-warp smem (C-layout -> A-layout relabeling via smem)
#pragma unroll
        for (int nt = 0; nt < 4; nt++) {
            int c0 = nt * 8 + 2 * tg;
            Pw[g * PS_LD + c0] = s[nt][0];
            Pw[g * PS_LD + c0 + 1] = s[nt][1];
            Pw[(g + 8) * PS_LD + c0] = s[nt][2];
            Pw[(g + 8) * PS_LD + c0 + 1] = s[nt][3];
        }
        __syncwarp();

        // O += P V : 16x32 per warp, 16 mmas
#pragma unroll
        for (int kc = 0; kc < 4; kc++) {
            int kb = kc * 8;
            uint32_t af[4];
            af[0] = __float_as_uint(Pw[g * PS_LD + kb + tg]);
            af[1] = __float_as_uint(Pw[(g + 8) * PS_LD + kb + tg]);
            af[2] = __float_as_uint(Pw[g * PS_LD + kb + tg + 4]);
            af[3] = __float_as_uint(Pw[(g + 8) * PS_LD + kb + tg + 4]);
#pragma unroll
            for (int nt = 0; nt < 4; nt++) {
                int cn = nt * 8 + g;
                uint32_t bf[2];
                bf[0] = __float_as_uint(Vs[cn * VS_LD + kb + tg]);
                bf[1] = __float_as_uint(Vs[cn * VS_LD + kb + tg + 4]);
                mma1688(oacc[nt], af, bf);
            }
        }
        __syncwarp();
    }

    // normalize + transpose through smem (reuse Ps), coalesced store
    __syncthreads();
    float inv0 = 1.f / lrow[0], inv1 = 1.f / lrow[1];
    float* Os = Ps;
#pragma unroll
    for (int nt = 0; nt < 4; nt++) {
        int d = nt * 8 + tg * 2;
        int irow = w * 16 + g;
        Os[d * OSL + irow] = oacc[nt][0] * inv0;
        Os[(d + 1) * OSL + irow] = oacc[nt][1] * inv0;
        Os[d * OSL + irow + 8] = oacc[nt][2] * inv1;
        Os[(d + 1) * OSL + irow + 8] = oacc[nt][3] * inv1;
    }
    __syncthreads();

    float* ob = out + ((long)b * 256 + h * 32) * 1024;
#pragma unroll
    for (int p = 0; p < 4; p++) {
        int idx = p * 256 + tid;
        int c = idx >> 5, i4 = idx & 31;
        float4 v = *(const float4*)&Os[c * OSL + i4 * 4];
        *(float4*)&ob[(long)c * 1024 + i0 + i4 * 4] = v;
    }
}

// ---------------------------------------------------------------------------
// GroupNorm(8) + affine + residual. One block per (b, group), 512 threads.
// ---------------------------------------------------------------------------
__global__ void __launch_bounds__(512) gn_kernel(const float* __restrict__ proj,
                                                 const float* __restrict__ x,
                                                 const float* __restrict__ gamma,
                                                 const float* __restrict__ beta,
                                                 float* __restrict__ out) {
    const int b = blockIdx.x >> 3;
    const int g = blockIdx.x & 7;
    const long base = ((long)b * CC + g * 32) * HW;
    const float4* p4 = (const float4*)(proj + base);
    const float4* x4 = (const float4*)(x + base);
    float4* o4 = (float4*)(out + base);
    const int N4 = 8192;

    float s = 0.f, q = 0.f;
#pragma unroll 4
    for (int i = threadIdx.x; i < N4; i += 512) {
        float4 v = p4[i];
        s += v.x + v.y + v.z + v.w;
        q = fmaf(v.x, v.x, q); q = fmaf(v.y, v.y, q);
        q = fmaf(v.z, v.z, q); q = fmaf(v.w, v.w, q);
    }
    __shared__ float ss[16], sq[16];
    const int lane = threadIdx.x & 31, wid = threadIdx.x >> 5;
#pragma unroll
    for (int o = 16; o > 0; o >>= 1) {
        s += __shfl_xor_sync(0xffffffffu, s, o);
        q += __shfl_xor_sync(0xffffffffu, q, o);
    }
    if (lane == 0) { ss[wid] = s; sq[wid] = q; }
    __syncthreads();
    __shared__ float s_mean, s_inv;
    if (threadIdx.x == 0) {
        float ts = 0.f, tq = 0.f;
#pragma unroll
        for (int i = 0; i < 16; i++) { ts += ss[i]; tq += sq[i]; }
        float mean = ts / 32768.f;
        float var = tq / 32768.f - mean * mean;
        s_mean = mean;
        s_inv = rsqrtf(var + GN_EPS);
    }
    __syncthreads();
    const float mean = s_mean, inv = s_inv;

#pragma unroll 4
    for (int i = threadIdx.x; i < N4; i += 512) {
        int c = g * 32 + (i >> 8);
        float ga = gamma[c] * inv, be = beta[c];
        float4 v = p4[i], xv = x4[i], o;
        o.x = (v.x - mean) * ga + be + xv.x;
        o.y = (v.y - mean) * ga + be + xv.y;
        o.z = (v.z - mean) * ga + be + xv.z;
        o.w = (v.w - mean) * ga + be + xv.w;
        o4[i] = o;
    }
}

// ---------------------------------------------------------------------------
extern "C" void kernel_launch(void* const* d_in, const int* in_sizes, int n_in,
                              void* d_out, int out_size) {
    const float* x      = (const float*)d_in[0];
    const float* w_qkv  = (const float*)d_in[1];
    const float* w_proj = (const float*)d_in[2];
    const float* gamma  = (const float*)d_in[3];
    const float* beta   = (const float*)d_in[4];
    float* out = (float*)d_out;

    float *qkv_p, *attn_p, *proj_p;
    cudaGetSymbolAddress((void**)&qkv_p, g_qkv);
    cudaGetSymbolAddress((void**)&attn_p, g_attn);
    cudaGetSymbolAddress((void**)&proj_p, g_proj);

    // 1) qkv GEMM: W[768,256] * X_b[256,1024]
    mma_gemm<<<dim3(8, 12, 16), 256>>>(w_qkv, x, qkv_p,
                                       (long)CC * HW, (long)3 * CC * HW);
    // 2) attention (tf32)
    attn_tf32<<<dim3(128, 8), 256>>>(qkv_p, attn_p);
    // 3) proj GEMM: Wp[256,256] * attn_b[256,1024]
    mma_gemm<<<dim3(8, 4, 16), 256>>>(w_proj, attn_p, proj_p,
                                      (long)CC * HW, (long)CC * HW);
    // 4) GroupNorm + residual
    gn_kernel<<<BB * GN_G, 512>>>(proj_p, x, gamma, beta, out);
}

// round 6
// speedup vs baseline: 2.9250x; 1.1262x over previous
#include <cuda_runtime.h>
#include <cuda_bf16.h>
#include <math.h>
#include <stdint.h>

#define BB 16
#define CC 256
#define HW 1024
#define NH 8
#define HD 32
#define GN_G 8
#define GN_EPS 1e-5f

// Scratch
__device__ float g_qkv[BB * 3 * CC * HW];   // [b][o(768)][s]
__device__ float g_attn[BB * CC * HW];      // [b][c][s]
__device__ float g_proj[BB * CC * HW];      // [b][c][s]

// ---------------------------------------------------------------------------
// helpers
// ---------------------------------------------------------------------------
// tf32 mma m16n8k8
__device__ __forceinline__ void mma1688(float* c, const uint32_t* a, const uint32_t* b) {
    asm volatile(
        "mma.sync.aligned.m16n8k8.row.col.f32.tf32.tf32.f32 "
        "{%0,%1,%2,%3}, {%4,%5,%6,%7}, {%8,%9}, {%0,%1,%2,%3};"
        : "+f"(c[0]), "+f"(c[1]), "+f"(c[2]), "+f"(c[3])
        : "r"(a[0]), "r"(a[1]), "r"(a[2]), "r"(a[3]), "r"(b[0]), "r"(b[1]));
}
__device__ __forceinline__ uint32_t tf32r(float v) {
    uint32_t r;
    asm("cvt.rna.tf32.f32 %0, %1;" : "=r"(r) : "f"(v));
    return r;
}

// ---------------------------------------------------------------------------
// Batched GEMM via single-pass tf32 mma. fp32 in/out, rna rounding.
// C[b] = W[M,256] * X[b][256,1024].  BM=64, BN=128, BK=32, 256 threads.
// ---------------------------------------------------------------------------
#define WLDA 36     // 32 + 4 pad: a-frag addr%32 = 4g+tg (conflict-free), 144B rows
#define XLDB 132    // 128 + 4 pad: b-frag addr%32 = 4tg+g (conflict-free), 528B rows

__global__ void __launch_bounds__(256) tf32_gemm(const float* __restrict__ A,
                                                 const float* __restrict__ B,
                                                 float* __restrict__ C,
                                                 long sB, long sC) {
    const int bz = blockIdx.z;
    const float* Bp = B + (long)bz * sB;
    float* Cp = C + (long)bz * sC;
    const int m0 = blockIdx.y * 64, n0 = blockIdx.x * 128;
    const int tid = threadIdx.x, w = tid >> 5, lane = tid & 31;
    const int g = lane >> 2, tg = lane & 3;
    const int wm = w >> 2, wn = w & 3;

    __shared__ uint32_t Ws[64 * WLDA];   // 9216 B
    __shared__ uint32_t Xs[32 * XLDB];   // 16896 B

    float acc[2][4][4];
#pragma unroll
    for (int mt = 0; mt < 2; mt++)
#pragma unroll
        for (int nt = 0; nt < 4; nt++)
#pragma unroll
            for (int i = 0; i < 4; i++) acc[mt][nt][i] = 0.f;

    for (int k0 = 0; k0 < 256; k0 += 32) {
        // stage global loads in registers (float4)
        float4 wv[2], xv[4];
#pragma unroll
        for (int p = 0; p < 2; p++) {
            int idx4 = p * 256 + tid;           // 512 float4 = 64x32
            int r = idx4 >> 3, c4 = idx4 & 7;
            wv[p] = *(const float4*)&A[(m0 + r) * 256 + k0 + c4 * 4];
        }
#pragma unroll
        for (int p = 0; p < 4; p++) {
            int idx4 = p * 256 + tid;           // 1024 float4 = 32x128
            int r = idx4 >> 5, c4 = idx4 & 31;
            xv[p] = *(const float4*)&Bp[(long)(k0 + r) * 1024 + n0 + c4 * 4];
        }
        __syncthreads();
#pragma unroll
        for (int p = 0; p < 2; p++) {
            int idx4 = p * 256 + tid;
            int r = idx4 >> 3, c4 = idx4 & 7;
            uint4 u = make_uint4(tf32r(wv[p].x), tf32r(wv[p].y),
                                 tf32r(wv[p].z), tf32r(wv[p].w));
            *(uint4*)&Ws[r * WLDA + c4 * 4] = u;
        }
#pragma unroll
        for (int p = 0; p < 4; p++) {
            int idx4 = p * 256 + tid;
            int r = idx4 >> 5, c4 = idx4 & 31;
            uint4 u = make_uint4(tf32r(xv[p].x), tf32r(xv[p].y),
                                 tf32r(xv[p].z), tf32r(xv[p].w));
            *(uint4*)&Xs[r * XLDB + c4 * 4] = u;
        }
        __syncthreads();

#pragma unroll
        for (int kc = 0; kc < 4; kc++) {
            const int kb = kc * 8;
            uint32_t af[2][4];
#pragma unroll
            for (int mt = 0; mt < 2; mt++) {
                int rb = wm * 32 + mt * 16 + g;
                af[mt][0] = Ws[rb * WLDA + kb + tg];
                af[mt][1] = Ws[(rb + 8) * WLDA + kb + tg];
                af[mt][2] = Ws[rb * WLDA + kb + tg + 4];
                af[mt][3] = Ws[(rb + 8) * WLDA + kb + tg + 4];
            }
            uint32_t bf[4][2];
#pragma unroll
            for (int nt = 0; nt < 4; nt++) {
                int cn = wn * 32 + nt * 8 + g;
                bf[nt][0] = Xs[(kb + tg) * XLDB + cn];
                bf[nt][1] = Xs[(kb + tg + 4) * XLDB + cn];
            }
#pragma unroll
            for (int mt = 0; mt < 2; mt++)
#pragma unroll
                for (int nt = 0; nt < 4; nt++)
                    mma1688(acc[mt][nt], af[mt], bf[nt]);
        }
        __syncthreads();
    }

#pragma unroll
    for (int mt = 0; mt < 2; mt++)
#pragma unroll
        for (int nt = 0; nt < 4; nt++) {
            int row = m0 + wm * 32 + mt * 16 + g;
            int col = n0 + wn * 32 + nt * 8 + tg * 2;
            *(float2*)&Cp[(long)row * 1024 + col] =
                make_float2(acc[mt][nt][0], acc[mt][nt][1]);
            *(float2*)&Cp[(long)(row + 8) * 1024 + col] =
                make_float2(acc[mt][nt][2], acc[mt][nt][3]);
        }
}

// ---------------------------------------------------------------------------
// Flash attention via single-pass tf32 mma (m16n8k8), fp32 softmax.
// 256 threads (8 warps), 128 queries per block, key chunks of 32.
// grid: (128 bh, 8 qtiles)
// ---------------------------------------------------------------------------
#define PS_LD 40
#define KS_LD 40
#define VS_LD 36
#define OSL 132

__global__ void __launch_bounds__(256) attn_tf32(const float* __restrict__ qkv,
                                                 float* __restrict__ out) {
    __shared__ float Ps[8 * 16 * PS_LD];   // 20480 B (reused as Os in epilogue)
    __shared__ float Ks[32 * KS_LD];       // 5120 B
    __shared__ float Vs[32 * VS_LD];       // 4608 B

    const int bh = blockIdx.x;
    const int b = bh >> 3, h = bh & 7;
    const int i0 = blockIdx.y * 128;
    const float* qg = qkv + ((long)b * 768 + h * 32) * 1024;
    const float* kg = qg + 256 * 1024;
    const float* vg = qg + 512 * 1024;

    const int tid = threadIdx.x, w = tid >> 5, lane = tid & 31;
    const int g = lane >> 2, tg = lane & 3;
    const float scale = 0.17677669529663687f;  // 1/sqrt(32)

    // Q fragments direct from global, pre-scaled, rna-rounded to tf32.
    uint32_t qf[4][4];
    {
        const int r0 = i0 + w * 16 + g;
#pragma unroll
        for (int kc = 0; kc < 4; kc++) {
            int d0 = kc * 8 + tg, d1 = d0 + 4;
            qf[kc][0] = tf32r(qg[(long)d0 * 1024 + r0] * scale);
            qf[kc][1] = tf32r(qg[(long)d0 * 1024 + r0 + 8] * scale);
            qf[kc][2] = tf32r(qg[(long)d1 * 1024 + r0] * scale);
            qf[kc][3] = tf32r(qg[(long)d1 * 1024 + r0 + 8] * scale);
        }
    }

    float mrow[2] = {-1e30f, -1e30f};
    float lrow[2] = {0.f, 0.f};
    float oacc[4][4];
#pragma unroll
    for (int nt = 0; nt < 4; nt++)
#pragma unroll
        for (int i = 0; i < 4; i++) oacc[nt][i] = 0.f;

    float* Pw = Ps + w * 16 * PS_LD;

    for (int j0 = 0; j0 < HW; j0 += 32) {
        __syncthreads();
#pragma unroll
        for (int p = 0; p < 4; p++) {
            int idx = p * 256 + tid;
            int j = idx & 31, d = idx >> 5;
            Ks[d * KS_LD + j] = __uint_as_float(tf32r(kg[(long)d * 1024 + j0 + j]));
            Vs[d * VS_LD + j] = __uint_as_float(tf32r(vg[(long)d * 1024 + j0 + j]));
        }
        __syncthreads();

        // S = Q K^T : 16x32 per warp
        float s[4][4];
#pragma unroll
        for (int nt = 0; nt < 4; nt++)
#pragma unroll
            for (int i = 0; i < 4; i++) s[nt][i] = 0.f;
#pragma unroll
        for (int kc = 0; kc < 4; kc++) {
            int kb = kc * 8;
#pragma unroll
            for (int nt = 0; nt < 4; nt++) {
                int cn = nt * 8 + g;
                uint32_t bf[2];
                bf[0] = __float_as_uint(Ks[(kb + tg) * KS_LD + cn]);
                bf[1] = __float_as_uint(Ks[(kb + tg + 4) * KS_LD + cn]);
                mma1688(s[nt], qf[kc], bf);
            }
        }

        // online softmax (rows g and g+8); l accumulated from tf32-rounded P
        float sc[2];
#pragma unroll
        for (int r = 0; r < 2; r++) {
            float mx = -1e30f;
#pragma unroll
            for (int nt = 0; nt < 4; nt++)
                mx = fmaxf(mx, fmaxf(s[nt][2 * r], s[nt][2 * r + 1]));
            mx = fmaxf(mx, __shfl_xor_sync(0xffffffffu, mx, 1));
            mx = fmaxf(mx, __shfl_xor_sync(0xffffffffu, mx, 2));
            float mn = fmaxf(mrow[r], mx);
            sc[r] = __expf(mrow[r] - mn);
            mrow[r] = mn;
            float ls = 0.f;
#pragma unroll
            for (int nt = 0; nt < 4; nt++) {
                float p0 = __uint_as_float(tf32r(__expf(s[nt][2 * r] - mn)));
                float p1 = __uint_as_float(tf32r(__expf(s[nt][2 * r + 1] - mn)));
                s[nt][2 * r] = p0;
                s[nt][2 * r + 1] = p1;
                ls += p0 + p1;
            }
            ls += __shfl_xor_sync(0xffffffffu, ls, 1);
            ls += __shfl_xor_sync(0xffffffffu, ls, 2);
            lrow[r] = lrow[r] * sc[r] + ls;
        }
#pragma unroll
        for (int nt = 0; nt < 4; nt++) {
            oacc[nt][0] *= sc[0];
            oacc[nt][1] *= sc[0];
            oacc[nt][2] *= sc[1];
            oacc[nt][3] *= sc[1];
        }

        // Stage P to per-warp smem (C-layout -> A-layout relabeling via smem)
#pragma unroll
        for (int nt = 0; nt < 4; nt++) {
            int c0 = nt * 8 + 2 * tg;
            Pw[g * PS_LD + c0] = s[nt][0];
            Pw[g * PS_LD + c0 + 1] = s[nt][1];
            Pw[(g + 8) * PS_LD + c0] = s[nt][2];
            Pw[(g + 8) * PS_LD + c0 + 1] = s[nt][3];
        }
        __syncwarp();

        // O += P V : 16x32 per warp
#pragma unroll
        for (int kc = 0; kc < 4; kc++) {
            int kb = kc * 8;
            uint32_t af[4];
            af[0] = __float_as_uint(Pw[g * PS_LD + kb + tg]);
            af[1] = __float_as_uint(Pw[(g + 8) * PS_LD + kb + tg]);
            af[2] = __float_as_uint(Pw[g * PS_LD + kb + tg + 4]);
            af[3] = __float_as_uint(Pw[(g + 8) * PS_LD + kb + tg + 4]);
#pragma unroll
            for (int nt = 0; nt < 4; nt++) {
                int cn = nt * 8 + g;
                uint32_t bf[2];
                bf[0] = __float_as_uint(Vs[cn * VS_LD + kb + tg]);
                bf[1] = __float_as_uint(Vs[cn * VS_LD + kb + tg + 4]);
                mma1688(oacc[nt], af, bf);
            }
        }
        __syncwarp();
    }

    // normalize + transpose through smem (reuse Ps), coalesced store
    __syncthreads();
    float inv0 = 1.f / lrow[0], inv1 = 1.f / lrow[1];
    float* Os = Ps;
#pragma unroll
    for (int nt = 0; nt < 4; nt++) {
        int d = nt * 8 + tg * 2;
        int irow = w * 16 + g;
        Os[d * OSL + irow] = oacc[nt][0] * inv0;
        Os[(d + 1) * OSL + irow] = oacc[nt][1] * inv0;
        Os[d * OSL + irow + 8] = oacc[nt][2] * inv1;
        Os[(d + 1) * OSL + irow + 8] = oacc[nt][3] * inv1;
    }
    __syncthreads();

    float* ob = out + ((long)b * 256 + h * 32) * 1024;
#pragma unroll
    for (int p = 0; p < 4; p++) {
        int idx = p * 256 + tid;
        int c = idx >> 5, i4 = idx & 31;
        float4 v = *(const float4*)&Os[c * OSL + i4 * 4];
        *(float4*)&ob[(long)c * 1024 + i0 + i4 * 4] = v;
    }
}

// ---------------------------------------------------------------------------
// GroupNorm(8) + affine + residual. One block per (b, group), 512 threads.
// ---------------------------------------------------------------------------
__global__ void __launch_bounds__(512) gn_kernel(const float* __restrict__ proj,
                                                 const float* __restrict__ x,
                                                 const float* __restrict__ gamma,
                                                 const float* __restrict__ beta,
                                                 float* __restrict__ out) {
    const int b = blockIdx.x >> 3;
    const int g = blockIdx.x & 7;
    const long base = ((long)b * CC + g * 32) * HW;
    const float4* p4 = (const float4*)(proj + base);
    const float4* x4 = (const float4*)(x + base);
    float4* o4 = (float4*)(out + base);
    const int N4 = 8192;

    float s = 0.f, q = 0.f;
#pragma unroll 4
    for (int i = threadIdx.x; i < N4; i += 512) {
        float4 v = p4[i];
        s += v.x + v.y + v.z + v.w;
        q = fmaf(v.x, v.x, q); q = fmaf(v.y, v.y, q);
        q = fmaf(v.z, v.z, q); q = fmaf(v.w, v.w, q);
    }
    __shared__ float ss[16], sq[16];
    const int lane = threadIdx.x & 31, wid = threadIdx.x >> 5;
#pragma unroll
    for (int o = 16; o > 0; o >>= 1) {
        s += __shfl_xor_sync(0xffffffffu, s, o);
        q += __shfl_xor_sync(0xffffffffu, q, o);
    }
    if (lane == 0) { ss[wid] = s; sq[wid] = q; }
    __syncthreads();
    __shared__ float s_mean, s_inv;
    if (threadIdx.x == 0) {
        float ts = 0.f, tq = 0.f;
#pragma unroll
        for (int i = 0; i < 16; i++) { ts += ss[i]; tq += sq[i]; }
        float mean = ts / 32768.f;
        float var = tq / 32768.f - mean * mean;
        s_mean = mean;
        s_inv = rsqrtf(var + GN_EPS);
    }
    __syncthreads();
    const float mean = s_mean, inv = s_inv;

#pragma unroll 4
    for (int i = threadIdx.x; i < N4; i += 512) {
        int c = g * 32 + (i >> 8);
        float ga = gamma[c] * inv, be = beta[c];
        float4 v = p4[i], xv = x4[i], o;
        o.x = (v.x - mean) * ga + be + xv.x;
        o.y = (v.y - mean) * ga + be + xv.y;
        o.z = (v.z - mean) * ga + be + xv.z;
        o.w = (v.w - mean) * ga + be + xv.w;
        o4[i] = o;
    }
}

// ---------------------------------------------------------------------------
extern "C" void kernel_launch(void* const* d_in, const int* in_sizes, int n_in,
                              void* d_out, int out_size) {
    const float* x      = (const float*)d_in[0];
    const float* w_qkv  = (const float*)d_in[1];
    const float* w_proj = (const float*)d_in[2];
    const float* gamma  = (const float*)d_in[3];
    const float* beta   = (const float*)d_in[4];
    float* out = (float*)d_out;

    float *qkv_p, *attn_p, *proj_p;
    cudaGetSymbolAddress((void**)&qkv_p, g_qkv);
    cudaGetSymbolAddress((void**)&attn_p, g_attn);
    cudaGetSymbolAddress((void**)&proj_p, g_proj);

    // 1) qkv GEMM: W[768,256] * X_b[256,1024]
    tf32_gemm<<<dim3(8, 12, 16), 256>>>(w_qkv, x, qkv_p,
                                        (long)CC * HW, (long)3 * CC * HW);
    // 2) attention (tf32)
    attn_tf32<<<dim3(128, 8), 256>>>(qkv_p, attn_p);
    // 3) proj GEMM: Wp[256,256] * attn_b[256,1024]
    tf32_gemm<<<dim3(8, 4, 16), 256>>>(w_proj, attn_p, proj_p,
                                       (long)CC * HW, (long)CC * HW);
    // 4) GroupNorm + residual
    gn_kernel<<<BB * GN_G, 512>>>(proj_p, x, gamma, beta, out);
}

// round 7
// speedup vs baseline: 3.0934x; 1.0576x over previous
#include <cuda_runtime.h>
#include <cuda_bf16.h>
#include <math.h>
#include <stdint.h>

#define BB 16
#define CC 256
#define HW 1024
#define NH 8
#define HD 32
#define GN_G 8
#define GN_EPS 1e-5f

// Scratch
__device__ float g_qkv[BB * 3 * CC * HW];   // [b][o(768)][s]
__device__ float g_attn[BB * CC * HW];      // [b][c][s]
__device__ float g_proj[BB * CC * HW];      // [b][c][s]

// ---------------------------------------------------------------------------
// helpers
// ---------------------------------------------------------------------------
__device__ __forceinline__ void mma1688(float* c, const uint32_t* a, const uint32_t* b) {
    asm volatile(
        "mma.sync.aligned.m16n8k8.row.col.f32.tf32.tf32.f32 "
        "{%0,%1,%2,%3}, {%4,%5,%6,%7}, {%8,%9}, {%0,%1,%2,%3};"
        : "+f"(c[0]), "+f"(c[1]), "+f"(c[2]), "+f"(c[3])
        : "r"(a[0]), "r"(a[1]), "r"(a[2]), "r"(a[3]), "r"(b[0]), "r"(b[1]));
}
__device__ __forceinline__ uint32_t tf32r(float v) {
    uint32_t r;
    asm("cvt.rna.tf32.f32 %0, %1;" : "=r"(r) : "f"(v));
    return r;
}

// ---------------------------------------------------------------------------
// Batched GEMM via single-pass tf32 mma, software-pipelined global loads.
// C[b] = W[M,256] * X[b][256,1024].  BM=64, BN=128, BK=32, 256 threads.
// ---------------------------------------------------------------------------
#define WLDA 36
#define XLDB 132

__global__ void __launch_bounds__(256) tf32_gemm(const float* __restrict__ A,
                                                 const float* __restrict__ B,
                                                 float* __restrict__ C,
                                                 long sB, long sC) {
    const int bz = blockIdx.z;
    const float* Bp = B + (long)bz * sB;
    float* Cp = C + (long)bz * sC;
    const int m0 = blockIdx.y * 64, n0 = blockIdx.x * 128;
    const int tid = threadIdx.x, w = tid >> 5, lane = tid & 31;
    const int g = lane >> 2, tg = lane & 3;
    const int wm = w >> 2, wn = w & 3;

    __shared__ uint32_t Ws[64 * WLDA];   // 9216 B
    __shared__ uint32_t Xs[32 * XLDB];   // 16896 B

    float acc[2][4][4];
#pragma unroll
    for (int mt = 0; mt < 2; mt++)
#pragma unroll
        for (int nt = 0; nt < 4; nt++)
#pragma unroll
            for (int i = 0; i < 4; i++) acc[mt][nt][i] = 0.f;

    // addressing for staged loads
    const int wr = tid >> 3, wc4 = (tid & 7) * 4;         // W: 64x32 via 512 f4
    const int xr = tid >> 5, xc4 = (tid & 31) * 4;        // X: 32x128 via 1024 f4

    float4 wv[2], xv[4];
    // prologue: load k0 = 0
#pragma unroll
    for (int p = 0; p < 2; p++)
        wv[p] = *(const float4*)&A[(m0 + wr + p * 32) * 256 + wc4];
#pragma unroll
    for (int p = 0; p < 4; p++)
        xv[p] = *(const float4*)&Bp[(long)(xr + p * 8) * 1024 + n0 + xc4];

    for (int k0 = 0; k0 < 256; k0 += 32) {
        __syncthreads();
#pragma unroll
        for (int p = 0; p < 2; p++) {
            uint4 u = make_uint4(tf32r(wv[p].x), tf32r(wv[p].y),
                                 tf32r(wv[p].z), tf32r(wv[p].w));
            *(uint4*)&Ws[(wr + p * 32) * WLDA + wc4] = u;
        }
#pragma unroll
        for (int p = 0; p < 4; p++) {
            uint4 u = make_uint4(tf32r(xv[p].x), tf32r(xv[p].y),
                                 tf32r(xv[p].z), tf32r(xv[p].w));
            *(uint4*)&Xs[(xr + p * 8) * XLDB + xc4] = u;
        }
        __syncthreads();

        // prefetch next k-tile while mma runs
        if (k0 + 32 < 256) {
            const int kn = k0 + 32;
#pragma unroll
            for (int p = 0; p < 2; p++)
                wv[p] = *(const float4*)&A[(m0 + wr + p * 32) * 256 + kn + wc4];
#pragma unroll
            for (int p = 0; p < 4; p++)
                xv[p] = *(const float4*)&Bp[(long)(kn + xr + p * 8) * 1024 + n0 + xc4];
        }

#pragma unroll
        for (int kc = 0; kc < 4; kc++) {
            const int kb = kc * 8;
            uint32_t af[2][4];
#pragma unroll
            for (int mt = 0; mt < 2; mt++) {
                int rb = wm * 32 + mt * 16 + g;
                af[mt][0] = Ws[rb * WLDA + kb + tg];
                af[mt][1] = Ws[(rb + 8) * WLDA + kb + tg];
                af[mt][2] = Ws[rb * WLDA + kb + tg + 4];
                af[mt][3] = Ws[(rb + 8) * WLDA + kb + tg + 4];
            }
            uint32_t bf[4][2];
#pragma unroll
            for (int nt = 0; nt < 4; nt++) {
                int cn = wn * 32 + nt * 8 + g;
                bf[nt][0] = Xs[(kb + tg) * XLDB + cn];
                bf[nt][1] = Xs[(kb + tg + 4) * XLDB + cn];
            }
#pragma unroll
            for (int mt = 0; mt < 2; mt++)
#pragma unroll
                for (int nt = 0; nt < 4; nt++)
                    mma1688(acc[mt][nt], af[mt], bf[nt]);
        }
    }

#pragma unroll
    for (int mt = 0; mt < 2; mt++)
#pragma unroll
        for (int nt = 0; nt < 4; nt++) {
            int row = m0 + wm * 32 + mt * 16 + g;
            int col = n0 + wn * 32 + nt * 8 + tg * 2;
            *(float2*)&Cp[(long)row * 1024 + col] =
                make_float2(acc[mt][nt][0], acc[mt][nt][1]);
            *(float2*)&Cp[(long)(row + 8) * 1024 + col] =
                make_float2(acc[mt][nt][2], acc[mt][nt][3]);
        }
}

// ---------------------------------------------------------------------------
// Flash attention via tf32 mma, 64-key chunks, prefetched K/V.
// 256 threads (8 warps), 128 queries per block. grid: (128 bh, 8 qtiles)
// ---------------------------------------------------------------------------
#define PS_LD 72    // per-warp P tile 16 x 64
#define KS_LD 72    // Ks [d=32][j=64]
#define VS_LD 68    // Vs [d=32][j=64]
#define OSL 132

__global__ void __launch_bounds__(256) attn_tf32(const float* __restrict__ qkv,
                                                 float* __restrict__ out) {
    __shared__ float Ps[8 * 16 * PS_LD];   // 36864 B (reused as Os in epilogue)
    __shared__ float Ks[32 * KS_LD];       // 9216 B
    __shared__ float Vs[32 * VS_LD];       // 8704 B

    const int bh = blockIdx.x;
    const int b = bh >> 3, h = bh & 7;
    const int i0 = blockIdx.y * 128;
    const float* qg = qkv + ((long)b * 768 + h * 32) * 1024;
    const float* kg = qg + 256 * 1024;
    const float* vg = qg + 512 * 1024;

    const int tid = threadIdx.x, w = tid >> 5, lane = tid & 31;
    const int g = lane >> 2, tg = lane & 3;
    const float scale = 0.17677669529663687f;  // 1/sqrt(32)

    // Q fragments direct from global, pre-scaled, rna-rounded to tf32.
    uint32_t qf[4][4];
    {
        const int r0 = i0 + w * 16 + g;
#pragma unroll
        for (int kc = 0; kc < 4; kc++) {
            int d0 = kc * 8 + tg, d1 = d0 + 4;
            qf[kc][0] = tf32r(qg[(long)d0 * 1024 + r0] * scale);
            qf[kc][1] = tf32r(qg[(long)d0 * 1024 + r0 + 8] * scale);
            qf[kc][2] = tf32r(qg[(long)d1 * 1024 + r0] * scale);
            qf[kc][3] = tf32r(qg[(long)d1 * 1024 + r0 + 8] * scale);
        }
    }

    float mrow[2] = {-1e30f, -1e30f};
    float lrow[2] = {0.f, 0.f};
    float oacc[4][4];
#pragma unroll
    for (int nt = 0; nt < 4; nt++)
#pragma unroll
        for (int i = 0; i < 4; i++) oacc[nt][i] = 0.f;

    float* Pw = Ps + w * 16 * PS_LD;

    // K/V fill: 2048 elems each, 8 per thread. idx: j = &63, d = >>6
    const int fj = tid & 63, fd0 = tid >> 6;   // fd0 in 0..3, p adds 4*p

    float pre_k[8], pre_v[8];
#pragma unroll
    for (int p = 0; p < 8; p++) {
        int d = fd0 + p * 4;
        pre_k[p] = kg[(long)d * 1024 + fj];
        pre_v[p] = vg[(long)d * 1024 + fj];
    }

    for (int j0 = 0; j0 < HW; j0 += 64) {
        __syncthreads();
#pragma unroll
        for (int p = 0; p < 8; p++) {
            int d = fd0 + p * 4;
            Ks[d * KS_LD + fj] = __uint_as_float(tf32r(pre_k[p]));
            Vs[d * VS_LD + fj] = __uint_as_float(tf32r(pre_v[p]));
        }
        __syncthreads();

        if (j0 + 64 < HW) {
#pragma unroll
            for (int p = 0; p < 8; p++) {
                int d = fd0 + p * 4;
                pre_k[p] = kg[(long)d * 1024 + j0 + 64 + fj];
                pre_v[p] = vg[(long)d * 1024 + j0 + 64 + fj];
            }
        }

        // S = Q K^T : 16x64 per warp
        float s[8][4];
#pragma unroll
        for (int nt = 0; nt < 8; nt++)
#pragma unroll
            for (int i = 0; i < 4; i++) s[nt][i] = 0.f;
#pragma unroll
        for (int kc = 0; kc < 4; kc++) {
            int kb = kc * 8;
#pragma unroll
            for (int nt = 0; nt < 8; nt++) {
                int cn = nt * 8 + g;
                uint32_t bf[2];
                bf[0] = __float_as_uint(Ks[(kb + tg) * KS_LD + cn]);
                bf[1] = __float_as_uint(Ks[(kb + tg + 4) * KS_LD + cn]);
                mma1688(s[nt], qf[kc], bf);
            }
        }

        // online softmax (rows g and g+8); l accumulated from tf32-rounded P
        float sc[2];
#pragma unroll
        for (int r = 0; r < 2; r++) {
            float mx = -1e30f;
#pragma unroll
            for (int nt = 0; nt < 8; nt++)
                mx = fmaxf(mx, fmaxf(s[nt][2 * r], s[nt][2 * r + 1]));
            mx = fmaxf(mx, __shfl_xor_sync(0xffffffffu, mx, 1));
            mx = fmaxf(mx, __shfl_xor_sync(0xffffffffu, mx, 2));
            float mn = fmaxf(mrow[r], mx);
            sc[r] = __expf(mrow[r] - mn);
            mrow[r] = mn;
            float ls = 0.f;
#pragma unroll
            for (int nt = 0; nt < 8; nt++) {
                float p0 = __uint_as_float(tf32r(__expf(s[nt][2 * r] - mn)));
                float p1 = __uint_as_float(tf32r(__expf(s[nt][2 * r + 1] - mn)));
                s[nt][2 * r] = p0;
                s[nt][2 * r + 1] = p1;
                ls += p0 + p1;
            }
            ls += __shfl_xor_sync(0xffffffffu, ls, 1);
            ls += __shfl_xor_sync(0xffffffffu, ls, 2);
            lrow[r] = lrow[r] * sc[r] + ls;
        }
#pragma unroll
        for (int nt = 0; nt < 4; nt++) {
            oacc[nt][0] *= sc[0];
            oacc[nt][1] *= sc[0];
            oacc[nt][2] *= sc[1];
            oacc[nt][3] *= sc[1];
        }

        // Stage P to per-warp smem (C-layout -> A-layout relabeling)
#pragma unroll
        for (int nt = 0; nt < 8; nt++) {
            int c0 = nt * 8 + 2 * tg;
            Pw[g * PS_LD + c0] = s[nt][0];
            Pw[g * PS_LD + c0 + 1] = s[nt][1];
            Pw[(g + 8) * PS_LD + c0] = s[nt][2];
            Pw[(g + 8) * PS_LD + c0 + 1] = s[nt][3];
        }
        __syncwarp();

        // O += P V : 16x32 per warp, k = 64
#pragma unroll
        for (int kc = 0; kc < 8; kc++) {
            int kb = kc * 8;
            uint32_t af[4];
            af[0] = __float_as_uint(Pw[g * PS_LD + kb + tg]);
            af[1] = __float_as_uint(Pw[(g + 8) * PS_LD + kb + tg]);
            af[2] = __float_as_uint(Pw[g * PS_LD + kb + tg + 4]);
            af[3] = __float_as_uint(Pw[(g + 8) * PS_LD + kb + tg + 4]);
#pragma unroll
            for (int nt = 0; nt < 4; nt++) {
                int cn = nt * 8 + g;
                uint32_t bf[2];
                bf[0] = __float_as_uint(Vs[cn * VS_LD + kb + tg]);
                bf[1] = __float_as_uint(Vs[cn * VS_LD + kb + tg + 4]);
                mma1688(oacc[nt], af, bf);
            }
        }
        __syncwarp();
    }

    // normalize + transpose through smem (reuse Ps), coalesced store
    __syncthreads();
    float inv0 = 1.f / lrow[0], inv1 = 1.f / lrow[1];
    float* Os = Ps;
#pragma unroll
    for (int nt = 0; nt < 4; nt++) {
        int d = nt * 8 + tg * 2;
        int irow = w * 16 + g;
        Os[d * OSL + irow] = oacc[nt][0] * inv0;
        Os[(d + 1) * OSL + irow] = oacc[nt][1] * inv0;
        Os[d * OSL + irow + 8] = oacc[nt][2] * inv1;
        Os[(d + 1) * OSL + irow + 8] = oacc[nt][3] * inv1;
    }
    __syncthreads();

    float* ob = out + ((long)b * 256 + h * 32) * 1024;
#pragma unroll
    for (int p = 0; p < 4; p++) {
        int idx = p * 256 + tid;
        int c = idx >> 5, i4 = idx & 31;
        float4 v = *(const float4*)&Os[c * OSL + i4 * 4];
        *(float4*)&ob[(long)c * 1024 + i0 + i4 * 4] = v;
    }
}

// ---------------------------------------------------------------------------
// GroupNorm(8) + affine + residual. One block per (b, group), 512 threads.
// ---------------------------------------------------------------------------
__global__ void __launch_bounds__(512) gn_kernel(const float* __restrict__ proj,
                                                 const float* __restrict__ x,
                                                 const float* __restrict__ gamma,
                                                 const float* __restrict__ beta,
                                                 float* __restrict__ out) {
    const int b = blockIdx.x >> 3;
    const int g = blockIdx.x & 7;
    const long base = ((long)b * CC + g * 32) * HW;
    const float4* p4 = (const float4*)(proj + base);
    const float4* x4 = (const float4*)(x + base);
    float4* o4 = (float4*)(out + base);
    const int N4 = 8192;

    float s = 0.f, q = 0.f;
#pragma unroll 4
    for (int i = threadIdx.x; i < N4; i += 512) {
        float4 v = p4[i];
        s += v.x + v.y + v.z + v.w;
        q = fmaf(v.x, v.x, q); q = fmaf(v.y, v.y, q);
        q = fmaf(v.z, v.z, q); q = fmaf(v.w, v.w, q);
    }
    __shared__ float ss[16], sq[16];
    const int lane = threadIdx.x & 31, wid = threadIdx.x >> 5;
#pragma unroll
    for (int o = 16; o > 0; o >>= 1) {
        s += __shfl_xor_sync(0xffffffffu, s, o);
        q += __shfl_xor_sync(0xffffffffu, q, o);
    }
    if (lane == 0) { ss[wid] = s; sq[wid] = q; }
    __syncthreads();
    __shared__ float s_mean, s_inv;
    if (threadIdx.x == 0) {
        float ts = 0.f, tq = 0.f;
#pragma unroll
        for (int i = 0; i < 16; i++) { ts += ss[i]; tq += sq[i]; }
        float mean = ts / 32768.f;
        float var = tq / 32768.f - mean * mean;
        s_mean = mean;
        s_inv = rsqrtf(var + GN_EPS);
    }
    __syncthreads();
    const float mean = s_mean, inv = s_inv;

#pragma unroll 4
    for (int i = threadIdx.x; i < N4; i += 512) {
        int c = g * 32 + (i >> 8);
        float ga = gamma[c] * inv, be = beta[c];
        float4 v = p4[i], xv = x4[i], o;
        o.x = (v.x - mean) * ga + be + xv.x;
        o.y = (v.y - mean) * ga + be + xv.y;
        o.z = (v.z - mean) * ga + be + xv.z;
        o.w = (v.w - mean) * ga + be + xv.w;
        o4[i] = o;
    }
}

// ---------------------------------------------------------------------------
extern "C" void kernel_launch(void* const* d_in, const int* in_sizes, int n_in,
                              void* d_out, int out_size) {
    const float* x      = (const float*)d_in[0];
    const float* w_qkv  = (const float*)d_in[1];
    const float* w_proj = (const float*)d_in[2];
    const float* gamma  = (const float*)d_in[3];
    const float* beta   = (const float*)d_in[4];
    float* out = (float*)d_out;

    float *qkv_p, *attn_p, *proj_p;
    cudaGetSymbolAddress((void**)&qkv_p, g_qkv);
    cudaGetSymbolAddress((void**)&attn_p, g_attn);
    cudaGetSymbolAddress((void**)&proj_p, g_proj);

    // 1) qkv GEMM: W[768,256] * X_b[256,1024]
    tf32_gemm<<<dim3(8, 12, 16), 256>>>(w_qkv, x, qkv_p,
                                        (long)CC * HW, (long)3 * CC * HW);
    // 2) attention (tf32, 64-key chunks)
    attn_tf32<<<dim3(128, 8), 256>>>(qkv_p, attn_p);
    // 3) proj GEMM: Wp[256,256] * attn_b[256,1024]
    tf32_gemm<<<dim3(8, 4, 16), 256>>>(w_proj, attn_p, proj_p,
                                       (long)CC * HW, (long)CC * HW);
    // 4) GroupNorm + residual
    gn_kernel<<<BB * GN_G, 512>>>(proj_p, x, gamma, beta, out);
}